// round 2
// baseline (speedup 1.0000x reference)
#include <cuda_runtime.h>

// score[e] = sum_d h[src[e], d] * h[dst[e], d]
// h: [100000, 32] fp32 ; src/dst: int32 [E] (JAX x64-disabled downgrades
// jnp.int64 -> int32!) ; out: fp32 [E]
//
// Strategy: 8 threads per edge. Each thread loads one float4 (16B) from the
// src row and one from the dst row, so each 8-lane group touches exactly one
// 128B line per gathered row -> minimal L1tex wavefronts. h (12.8 MB) fits
// entirely in L2, so this is an L2-bandwidth-bound gather.

static constexpr int D = 32;          // feature dim
static constexpr int LANES_PER_EDGE = 8;

__global__ __launch_bounds__(256) void edge_dot_kernel(
    const float* __restrict__ h,
    const int* __restrict__ src,
    const int* __restrict__ dst,
    float* __restrict__ out,
    int E)
{
    int gid = blockIdx.x * blockDim.x + threadIdx.x;
    int e = gid >> 3;        // edge index
    int i = gid & 7;         // lane within 8-thread group
    if (e >= E) return;

    int s = src[e];          // broadcast load within the 8-lane group
    int d = dst[e];

    const float4* __restrict__ hs =
        reinterpret_cast<const float4*>(h + (long long)s * D);
    const float4* __restrict__ hd =
        reinterpret_cast<const float4*>(h + (long long)d * D);

    float4 a = hs[i];
    float4 b = hd[i];
    float p = a.x * b.x + a.y * b.y + a.z * b.z + a.w * b.w;

    // reduce across the 8-lane group (lanes [8k .. 8k+7] share an edge)
    p += __shfl_xor_sync(0xFFFFFFFFu, p, 1);
    p += __shfl_xor_sync(0xFFFFFFFFu, p, 2);
    p += __shfl_xor_sync(0xFFFFFFFFu, p, 4);

    if (i == 0) out[e] = p;
}

extern "C" void kernel_launch(void* const* d_in, const int* in_sizes, int n_in,
                              void* d_out, int out_size)
{
    const float* h   = (const float*)d_in[0];
    const int*   src = (const int*)d_in[1];
    const int*   dst = (const int*)d_in[2];
    float*       out = (float*)d_out;

    int E = in_sizes[1];                    // number of edges
    long long total_threads = (long long)E * LANES_PER_EDGE;
    int block = 256;
    int grid = (int)((total_threads + block - 1) / block);

    edge_dot_kernel<<<grid, block>>>(h, src, dst, out, E);
}

// round 3
// speedup vs baseline: 1.4459x; 1.4459x over previous
#include <cuda_runtime.h>

// score[e] = sum_d h[src[e], d] * h[dst[e], d]
// h: [100000, 32] fp32 ; src/dst: int32 [E] ; out: fp32 [E]
//
// 8 lanes per edge-group, 4 edges per group:
//  - 2x int4 broadcast index loads per thread (4 edges' src + dst)
//  - 8 independent float4 gathers (MLP=8, each 8-lane group touches one
//    128B line per gathered row)
//  - 4 dot products, shuffle-reduce over the 8-lane group
//  - lane 0 stores float4 (4 scores) -> coalesced 64B store per warp

static constexpr int D = 32;
static constexpr int EDGES_PER_GROUP = 4;

__device__ __forceinline__ float dot4(float4 a, float4 b) {
    return a.x * b.x + a.y * b.y + a.z * b.z + a.w * b.w;
}

__device__ __forceinline__ float red8(float p) {
    p += __shfl_xor_sync(0xFFFFFFFFu, p, 1);
    p += __shfl_xor_sync(0xFFFFFFFFu, p, 2);
    p += __shfl_xor_sync(0xFFFFFFFFu, p, 4);
    return p;
}

__global__ __launch_bounds__(256) void edge_dot_kernel(
    const float* __restrict__ h,
    const int* __restrict__ src,
    const int* __restrict__ dst,
    float* __restrict__ out,
    int E)
{
    int gid = blockIdx.x * blockDim.x + threadIdx.x;
    int g = gid >> 3;                 // 8-lane group index
    int i = gid & 7;                  // lane within group
    long long e0 = (long long)g * EDGES_PER_GROUP;
    if (e0 >= E) return;

    if (e0 + EDGES_PER_GROUP <= E) {
        // broadcast loads: all 8 lanes of a group read the same int4
        int4 s4 = *reinterpret_cast<const int4*>(src + e0);
        int4 d4 = *reinterpret_cast<const int4*>(dst + e0);

        // 8 independent gathers
        float4 a0 = reinterpret_cast<const float4*>(h + (long long)s4.x * D)[i];
        float4 b0 = reinterpret_cast<const float4*>(h + (long long)d4.x * D)[i];
        float4 a1 = reinterpret_cast<const float4*>(h + (long long)s4.y * D)[i];
        float4 b1 = reinterpret_cast<const float4*>(h + (long long)d4.y * D)[i];
        float4 a2 = reinterpret_cast<const float4*>(h + (long long)s4.z * D)[i];
        float4 b2 = reinterpret_cast<const float4*>(h + (long long)d4.z * D)[i];
        float4 a3 = reinterpret_cast<const float4*>(h + (long long)s4.w * D)[i];
        float4 b3 = reinterpret_cast<const float4*>(h + (long long)d4.w * D)[i];

        float p0 = red8(dot4(a0, b0));
        float p1 = red8(dot4(a1, b1));
        float p2 = red8(dot4(a2, b2));
        float p3 = red8(dot4(a3, b3));

        if (i == 0)
            *reinterpret_cast<float4*>(out + e0) = make_float4(p0, p1, p2, p3);
    } else {
        // remainder (E not divisible by 4)
        for (long long e = e0; e < E; ++e) {
            int s = src[e];
            int d = dst[e];
            float4 a = reinterpret_cast<const float4*>(h + (long long)s * D)[i];
            float4 b = reinterpret_cast<const float4*>(h + (long long)d * D)[i];
            float p = red8(dot4(a, b));
            if (i == 0) out[e] = p;
        }
    }
}

extern "C" void kernel_launch(void* const* d_in, const int* in_sizes, int n_in,
                              void* d_out, int out_size)
{
    const float* h   = (const float*)d_in[0];
    const int*   src = (const int*)d_in[1];
    const int*   dst = (const int*)d_in[2];
    float*       out = (float*)d_out;

    int E = in_sizes[1];
    long long groups = ((long long)E + EDGES_PER_GROUP - 1) / EDGES_PER_GROUP;
    long long total_threads = groups * 8;
    int block = 256;
    int grid = (int)((total_threads + block - 1) / block);

    edge_dot_kernel<<<grid, block>>>(h, src, dst, out, E);
}